// round 17
// baseline (speedup 1.0000x reference)
#include <cuda_runtime.h>
#include <cuda_fp16.h>
#include <math.h>
#include <stdint.h>

// Problem constants
#define BB   2
#define LS   2048
#define DM   1024
#define DIN  2048
#define DST  16
#define RDT  64
#define ML   (BB*LS)      // 4096 rows
#define DFF  (4*DM)       // 4096

typedef __half fp16;

// ---------------- scratch (device globals) -----------------------------------
// xz16 unified: [ML][8192] fp16, cols [dir*4096..+2047]=xi, [+2048..+4095]=z
__device__ __align__(256) fp16  g_xz16[(size_t)ML * 8192];
__device__ __align__(256) fp16  g_xc16[2u * ML * DIN];
__device__ __align__(256) float g_xdbl[2u * ML * 96];    // cols 64..95: B/C interleaved
__device__ __align__(256) float g_dtu [2u * (size_t)ML * DIN * 2];  // (dt,u) fp32 pairs
__device__ __align__(256) fp16  g_sz16[2u * ML * DIN];   // silu(z) fp16
__device__ __align__(256) float g_xsum[(size_t)ML * DM];

__device__ __align__(256) fp16 g_x16 [(size_t)ML * DM];
__device__ __align__(256) fp16 g_y16 [(size_t)ML * 2 * DIN];   // [ML][dir*2048+d]
__device__ __align__(256) fp16 g_ln16[(size_t)ML * DM];
__device__ __align__(256) fp16 g_f116[(size_t)ML * DFF];
__device__ __align__(256) fp16 g_inw16 [2u * 2 * DIN * DM];
__device__ __align__(256) fp16 g_outw16c[(size_t)DM * 2 * DIN]; // [DM][dir*2048+k], x0.5
__device__ __align__(256) fp16 g_w116[(size_t)DFF * DM];
__device__ __align__(256) fp16 g_w216[(size_t)DM * DFF];

// ---------------- helpers ------------------------------------------------------
__device__ __forceinline__ float siluf(float v) { return v / (1.f + __expf(-v)); }
__device__ __forceinline__ float softplusf(float v) {
    return (v > 20.f) ? v : log1pf(__expf(v));
}

#define LDSM4(r0, r1, r2, r3, addr) \
    asm volatile("ldmatrix.sync.aligned.m8n8.x4.shared.b16 {%0,%1,%2,%3}, [%4];" \
        : "=r"(r0), "=r"(r1), "=r"(r2), "=r"(r3) : "r"(addr))

#define MMAF16(d, a, b0, b1) \
    asm volatile("mma.sync.aligned.m16n8k16.row.col.f32.f16.f16.f32 " \
        "{%0,%1,%2,%3}, {%4,%5,%6,%7}, {%8,%9}, {%0,%1,%2,%3};" \
        : "+f"((d)[0]), "+f"((d)[1]), "+f"((d)[2]), "+f"((d)[3]) \
        : "r"((a)[0]), "r"((a)[1]), "r"((a)[2]), "r"((a)[3]), "r"(b0), "r"(b1))

#define CPA16(sa, ga) \
    asm volatile("cp.async.cg.shared.global [%0], [%1], 16;" :: "r"(sa), "l"(ga))
#define CPA_COMMIT() asm volatile("cp.async.commit_group;" ::: "memory")
#define CPA_WAIT1()  asm volatile("cp.async.wait_group 1;" ::: "memory")

// ---------------- fp16 1-product tensor-core GEMM ------------------------------
#define KC       32
#define ARR_B    8192
#define STAGE_B  (2 * ARR_B)
#define NSTAGE   3
#define DSMEM2   (NSTAGE * STAGE_B)

__global__ __launch_bounds__(256, 2)
void mma_gemm2(const fp16* __restrict__ Af, int lda,
               const fp16* __restrict__ Bf, int ldb,
               const float* __restrict__ bias,
               const float* __restrict__ addsrc,
               float* __restrict__ Cf,
               fp16* __restrict__ C16,
               int ldc, int K, int act,
               size_t zsA, size_t zsB, size_t zsC)
{
    extern __shared__ char sm[];
    const int tid  = threadIdx.x;
    const int lane = tid & 31;
    const int wid  = tid >> 5;
    const int wm   = wid >> 2;
    const int wn   = wid & 3;
    const int rowBase = blockIdx.y * 128;
    const int colBase = blockIdx.x * 128;
    const size_t zA = (size_t)blockIdx.z * zsA;
    const size_t zB = (size_t)blockIdx.z * zsB;
    const size_t zC = (size_t)blockIdx.z * zsC;
    const uint32_t smb = (uint32_t)__cvta_generic_to_shared(sm);

    const int crow = tid >> 2;
    const int cck  = tid & 3;
    const size_t offA0 = zA + (size_t)(rowBase + crow) * lda + cck * 8;
    const size_t offA1 = zA + (size_t)(rowBase + crow + 64) * lda + cck * 8;
    const size_t offB0 = zB + (size_t)(colBase + crow) * ldb + cck * 8;
    const size_t offB1 = zB + (size_t)(colBase + crow + 64) * ldb + cck * 8;
    const uint32_t s0 = (uint32_t)crow * 64        + (uint32_t)((cck ^ ((crow >> 1) & 3)) * 16);
    const uint32_t s1 = (uint32_t)(crow + 64) * 64 + (uint32_t)((cck ^ (((crow + 64) >> 1) & 3)) * 16);

    const int laneAr = (lane & 7) + ((lane >> 3) & 1) * 8;
    const int aCk    = (lane >> 4);
    const int laneBr = (lane & 7) + ((lane >> 4) & 1) * 8;
    const int bCk    = (lane >> 3) & 1;
    uint32_t aRowB[4], aSw[4], bRowB[2], bSw[2];
    #pragma unroll
    for (int i = 0; i < 4; i++) {
        int r = wm * 64 + i * 16 + laneAr;
        aRowB[i] = (uint32_t)r * 64;
        aSw[i]   = (uint32_t)((r >> 1) & 3);
    }
    #pragma unroll
    for (int p = 0; p < 2; p++) {
        int r = wn * 32 + p * 16 + laneBr;
        bRowB[p] = (uint32_t)r * 64;
        bSw[p]   = (uint32_t)((r >> 1) & 3);
    }

    float acc[16][4];
    #pragma unroll
    for (int i = 0; i < 16; i++)
        #pragma unroll
        for (int j = 0; j < 4; j++) acc[i][j] = 0.f;

    const int nk = K / KC;

    auto issue = [&](int stg, int kt) {
        const uint32_t sb = smb + (uint32_t)stg * STAGE_B;
        const size_t ko = (size_t)kt * KC;
        CPA16(sb + 0*ARR_B + s0, Af + offA0 + ko);
        CPA16(sb + 0*ARR_B + s1, Af + offA1 + ko);
        CPA16(sb + 1*ARR_B + s0, Bf + offB0 + ko);
        CPA16(sb + 1*ARR_B + s1, Bf + offB1 + ko);
    };

    issue(0, 0); CPA_COMMIT();
    issue(1, 1); CPA_COMMIT();

    int stg = 0;
    for (int kt = 0; kt < nk; kt++) {
        CPA_WAIT1();
        __syncthreads();
        if (kt + 2 < nk) issue((stg + 2) % NSTAGE, kt + 2);
        CPA_COMMIT();

        const uint32_t base = smb + (uint32_t)stg * STAGE_B;
        #pragma unroll
        for (int ks = 0; ks < 2; ks++) {
            uint32_t aF[4][4], bF[2][4];
            #pragma unroll
            for (int i = 0; i < 4; i++)
                LDSM4(aF[i][0], aF[i][1], aF[i][2], aF[i][3],
                      base + 0*ARR_B + aRowB[i] + (((uint32_t)(ks*2 + aCk) ^ aSw[i]) * 16));
            #pragma unroll
            for (int p = 0; p < 2; p++)
                LDSM4(bF[p][0], bF[p][1], bF[p][2], bF[p][3],
                      base + 1*ARR_B + bRowB[p] + (((uint32_t)(ks*2 + bCk) ^ bSw[p]) * 16));
            #pragma unroll
            for (int i = 0; i < 4; i++)
                #pragma unroll
                for (int nt = 0; nt < 4; nt++)
                    MMAF16(acc[i*4+nt], aF[i], bF[nt>>1][(nt&1)*2], bF[nt>>1][(nt&1)*2+1]);
        }
        stg = (stg + 1) % NSTAGE;
    }

    const int erow  = wm * 64 + (lane >> 2);
    const int ecol0 = wn * 32 + (lane & 3) * 2;
    #pragma unroll
    for (int i = 0; i < 4; i++) {
        int r0 = rowBase + erow + i * 16;
        int r1 = r0 + 8;
        #pragma unroll
        for (int nt = 0; nt < 4; nt++) {
            int c = colBase + ecol0 + nt * 8;
            float v0 = acc[i*4+nt][0], v1 = acc[i*4+nt][1];
            float v2 = acc[i*4+nt][2], v3 = acc[i*4+nt][3];
            if (bias) {
                float b0 = __ldg(&bias[c]), b1 = __ldg(&bias[c+1]);
                v0 += b0; v1 += b1; v2 += b0; v3 += b1;
            }
            if (act == 1) { v0 = siluf(v0); v1 = siluf(v1); v2 = siluf(v2); v3 = siluf(v3); }
            else if (act == 2) { v0 = softplusf(v0); v1 = softplusf(v1); v2 = softplusf(v2); v3 = softplusf(v3); }
            if (addsrc) {
                v0 += addsrc[(size_t)r0 * ldc + c];
                v1 += addsrc[(size_t)r0 * ldc + c + 1];
                v2 += addsrc[(size_t)r1 * ldc + c];
                v3 += addsrc[(size_t)r1 * ldc + c + 1];
            }
            if (Cf) {
                *(float2*)&Cf[zC + (size_t)r0 * ldc + c] = make_float2(v0, v1);
                *(float2*)&Cf[zC + (size_t)r1 * ldc + c] = make_float2(v2, v3);
            } else {
                uint32_t u0 = (uint32_t)__half_as_ushort(__float2half_rn(v0)) |
                              ((uint32_t)__half_as_ushort(__float2half_rn(v1)) << 16);
                uint32_t u1 = (uint32_t)__half_as_ushort(__float2half_rn(v2)) |
                              ((uint32_t)__half_as_ushort(__float2half_rn(v3)) << 16);
                *(uint32_t*)(C16 + zC + (size_t)r0 * ldc + c) = u0;
                *(uint32_t*)(C16 + zC + (size_t)r1 * ldc + c) = u1;
            }
        }
    }
}

// ---------------- fp32 -> fp16 convert --------------------------------------------
__global__ void wcvt_kernel(const float* __restrict__ in,
                            fp16* __restrict__ out, int n4)
{
    int i = blockIdx.x * blockDim.x + threadIdx.x;
    if (i >= n4) return;
    float4 v = ((const float4*)in)[i];
    uint2 u;
    u.x = (uint32_t)__half_as_ushort(__float2half_rn(v.x)) |
          ((uint32_t)__half_as_ushort(__float2half_rn(v.y)) << 16);
    u.y = (uint32_t)__half_as_ushort(__float2half_rn(v.z)) |
          ((uint32_t)__half_as_ushort(__float2half_rn(v.w)) << 16);
    *(uint2*)(out + (size_t)i * 4) = u;
}

// ---- out_w convert: scale by 0.5, interleave dirs along K: out[c][dir*2048+k] ----
__global__ void wcvt_out_kernel(const float* __restrict__ in,  // [DM][DIN]
                                fp16* __restrict__ out,        // [DM][2*DIN]
                                int dir)
{
    int i = blockIdx.x * blockDim.x + threadIdx.x;
    if (i >= DM * DIN / 4) return;
    int c = i / (DIN / 4);
    int k = (i % (DIN / 4)) * 4;
    float4 v = ((const float4*)in)[i];
    uint2 u;
    u.x = (uint32_t)__half_as_ushort(__float2half_rn(0.5f * v.x)) |
          ((uint32_t)__half_as_ushort(__float2half_rn(0.5f * v.y)) << 16);
    u.y = (uint32_t)__half_as_ushort(__float2half_rn(0.5f * v.z)) |
          ((uint32_t)__half_as_ushort(__float2half_rn(0.5f * v.w)) << 16);
    *(uint2*)(out + (size_t)c * (2 * DIN) + dir * DIN + k) = u;
}

// ---------------- xdbl GEMM: fp16 A, [2][ML][96], B/C interleaved ---------------
__global__ __launch_bounds__(128)
void xdbl_gemm(const fp16* __restrict__ xcA,
               const float* __restrict__ xw0,
               const float* __restrict__ xw1,
               float* __restrict__ out)
{
    __shared__ float As[16][36];
    __shared__ float Bs[16][100];
    const int dir = blockIdx.z;
    const fp16* A = xcA + (size_t)dir * ML * DIN + (size_t)blockIdx.x * 32 * DIN;
    const float* B = dir ? xw1 : xw0;
    float* C = out + (size_t)dir * ML * 96 + (size_t)blockIdx.x * 32 * 96;

    const int tid = threadIdx.x;
    const int tx = tid & 15, ty = tid >> 4;
    float acc[4][6];
    #pragma unroll
    for (int i = 0; i < 4; i++)
        #pragma unroll
        for (int j = 0; j < 6; j++) acc[i][j] = 0.f;

    const int ar = tid >> 2, akc = (tid & 3) * 4;

    for (int k0 = 0; k0 < DIN; k0 += 16) {
        {
            uint2 raw = *(const uint2*)(A + (size_t)ar * DIN + k0 + akc);
            float2 f0 = __half22float2(*(__half2*)&raw.x);
            float2 f1 = __half22float2(*(__half2*)&raw.y);
            As[akc+0][ar] = f0.x; As[akc+1][ar] = f0.y;
            As[akc+2][ar] = f1.x; As[akc+3][ar] = f1.y;
        }
        #pragma unroll
        for (int j = 0; j < 3; j++) {
            int i = tid + j * 128;
            int n = i >> 2, kc = (i & 3) * 4;
            float4 v = *(const float4*)(B + (size_t)n * DIN + k0 + kc);
            Bs[kc+0][n] = v.x; Bs[kc+1][n] = v.y;
            Bs[kc+2][n] = v.z; Bs[kc+3][n] = v.w;
        }
        __syncthreads();
        #pragma unroll
        for (int kk = 0; kk < 16; kk++) {
            float4 a4 = *(const float4*)&As[kk][ty*4];
            float ar4[4] = {a4.x, a4.y, a4.z, a4.w};
            float2 b0 = *(const float2*)&Bs[kk][tx*6];
            float2 b1 = *(const float2*)&Bs[kk][tx*6+2];
            float2 b2 = *(const float2*)&Bs[kk][tx*6+4];
            float br[6] = {b0.x, b0.y, b1.x, b1.y, b2.x, b2.y};
            #pragma unroll
            for (int i = 0; i < 4; i++)
                #pragma unroll
                for (int j = 0; j < 6; j++)
                    acc[i][j] = fmaf(ar4[i], br[j], acc[i][j]);
        }
        __syncthreads();
    }
    #pragma unroll
    for (int i = 0; i < 4; i++)
        #pragma unroll
        for (int j = 0; j < 6; j++) {
            int c = tx*6 + j;
            int cw = (c < 64) ? c : ((c < 80) ? (64 + 2*(c - 64)) : (65 + 2*(c - 80)));
            C[(size_t)(ty*4+i) * 96 + cw] = acc[i][j];
        }
}

// ---------------- dt GEMM -> (dt,u) fp32 pairs + silu(z) fp16 --------------------
__global__ __launch_bounds__(256)
void dt_gemm(const float* __restrict__ xdblA,
             const fp16* __restrict__ xcA,
             const fp16* __restrict__ xz16,
             const float* __restrict__ w0, const float* __restrict__ w1,
             const float* __restrict__ b0, const float* __restrict__ b1,
             float* __restrict__ dtu,          // [2][ML][DIN][2]
             fp16* __restrict__ sz16)          // [2][ML][DIN]
{
    __shared__ float As[16][132];
    __shared__ float Bs[16][132];

    const int dir = blockIdx.z;
    const float* A = xdblA + (size_t)dir * ML * 96;
    const fp16* xcD = xcA + (size_t)dir * ML * DIN;
    const float* Bw = dir ? w1 : w0;
    const float* bias = dir ? b1 : b0;
    float* C = dtu + (size_t)dir * ML * DIN * 2;
    fp16* S = sz16 + (size_t)dir * ML * DIN;

    const int tid = threadIdx.x;
    const int tx = tid & 15;
    const int ty = tid >> 4;
    const int rowBase = blockIdx.y * 128;
    const int colBase = blockIdx.x * 128;

    const int lm = tid >> 1;
    const int lk = (tid & 1) * 8;

    const float* aPtr = A + (size_t)(rowBase + lm) * 96 + lk;
    const float* bPtr = Bw + (size_t)(colBase + lm) * RDT + lk;

    float acc[8][8];
    #pragma unroll
    for (int i = 0; i < 8; i++)
        #pragma unroll
        for (int j = 0; j < 8; j++) acc[i][j] = 0.f;

    for (int k0 = 0; k0 < RDT; k0 += 16) {
        float4 a0 = *(const float4*)(aPtr + k0);
        float4 a1 = *(const float4*)(aPtr + k0 + 4);
        float4 b0v = *(const float4*)(bPtr + k0);
        float4 b1v = *(const float4*)(bPtr + k0 + 4);

        As[lk+0][lm] = a0.x; As[lk+1][lm] = a0.y; As[lk+2][lm] = a0.z; As[lk+3][lm] = a0.w;
        As[lk+4][lm] = a1.x; As[lk+5][lm] = a1.y; As[lk+6][lm] = a1.z; As[lk+7][lm] = a1.w;
        Bs[lk+0][lm] = b0v.x; Bs[lk+1][lm] = b0v.y; Bs[lk+2][lm] = b0v.z; Bs[lk+3][lm] = b0v.w;
        Bs[lk+4][lm] = b1v.x; Bs[lk+5][lm] = b1v.y; Bs[lk+6][lm] = b1v.z; Bs[lk+7][lm] = b1v.w;
        __syncthreads();

        #pragma unroll
        for (int kk = 0; kk < 16; kk++) {
            float4 ra0 = *(const float4*)&As[kk][ty * 4];
            float4 ra1 = *(const float4*)&As[kk][64 + ty * 4];
            float4 rb0 = *(const float4*)&Bs[kk][tx * 4];
            float4 rb1 = *(const float4*)&Bs[kk][64 + tx * 4];
            float ar[8] = {ra0.x, ra0.y, ra0.z, ra0.w, ra1.x, ra1.y, ra1.z, ra1.w};
            float br[8] = {rb0.x, rb0.y, rb0.z, rb0.w, rb1.x, rb1.y, rb1.z, rb1.w};
            #pragma unroll
            for (int i = 0; i < 8; i++)
                #pragma unroll
                for (int j = 0; j < 8; j++)
                    acc[i][j] = fmaf(ar[i], br[j], acc[i][j]);
        }
        __syncthreads();
    }

    #pragma unroll
    for (int i = 0; i < 8; i++) {
        int r = rowBase + ((i < 4) ? (ty * 4 + i) : (64 + ty * 4 + i - 4));
        #pragma unroll
        for (int j = 0; j < 8; j += 2) {
            int c = colBase + ((j < 4) ? (tx * 4 + j) : (64 + tx * 4 + j - 4));
            float dt0 = softplusf(acc[i][j]   + bias[c]);
            float dt1 = softplusf(acc[i][j+1] + bias[c+1]);
            float2 uv = __half22float2(*(const __half2*)&xcD[(size_t)r * DIN + c]);
            *(float4*)&C[((size_t)r * DIN + c) * 2] = make_float4(dt0, uv.x, dt1, uv.y);

            __half2 zh = *(const __half2*)&xz16[(size_t)r * 8192 + dir * 4096 + 2048 + c];
            float sz0 = siluf(__low2float(zh));
            float sz1 = siluf(__high2float(zh));
            *(__half2*)&S[(size_t)r * DIN + c] = __floats2half2_rn(sz0, sz1);
        }
    }
}

// ---------------- depthwise causal conv, fp16 in/out, float4 over channels ------
__global__ void conv_kernel(const fp16* __restrict__ xz,
                            const float* __restrict__ cw0, const float* __restrict__ cw1,
                            const float* __restrict__ cb0, const float* __restrict__ cb1,
                            fp16* __restrict__ xc)
{
    int idx = blockIdx.x * blockDim.x + threadIdx.x;
    if (idx >= 2 * ML * DIN / 4) return;
    int dir = idx >= ML * DIN / 4;
    int li = dir ? (idx - ML * DIN / 4) : idx;
    int c4 = li & (DIN / 4 - 1);
    int r  = li / (DIN / 4);
    int l  = r & (LS - 1);
    int b  = r >> 11;
    int c  = c4 * 4;
    const float* cw = dir ? cw1 : cw0;
    const float* cb = dir ? cb1 : cb0;
    float4 w[4];
    #pragma unroll
    for (int q = 0; q < 4; q++) w[q] = *(const float4*)&cw[(c + q) * 4];
    float4 acc = *(const float4*)&cb[c];
    float* accp = &acc.x;

    const size_t colOff = (size_t)dir * 4096 + c;
    #pragma unroll
    for (int k = 0; k < 4; k++) {
        int lp = dir ? (l + 3 - k) : (l - 3 + k);
        bool ok = dir ? (lp < LS) : (lp >= 0);
        if (ok) {
            const __half2* hp = (const __half2*)&xz[(size_t)(b * LS + lp) * 8192 + colOff];
            float2 f0 = __half22float2(hp[0]);
            float2 f1 = __half22float2(hp[1]);
            float xp[4] = {f0.x, f0.y, f1.x, f1.y};
            #pragma unroll
            for (int q = 0; q < 4; q++) {
                float wt = (&w[q].x)[k];
                accp[q] = fmaf(xp[q], wt, accp[q]);
            }
        }
    }
    uint2 o;
    __half2 h0 = __floats2half2_rn(siluf(acc.x), siluf(acc.y));
    __half2 h1 = __floats2half2_rn(siluf(acc.z), siluf(acc.w));
    o.x = *(uint32_t*)&h0;
    o.y = *(uint32_t*)&h1;
    *(uint2*)&xc[(size_t)dir * ML * DIN + (size_t)r * DIN + c] = o;
}

// ---------------- selective scan: y out in [ML][dir*2048+d] layout ---------------
__global__ __launch_bounds__(256)
void scan_kernel(const float* __restrict__ dtu,   // [2][ML][DIN][2]
                 const fp16* __restrict__ sz16,   // [2][ML][DIN]
                 const float* __restrict__ xdbl,  // [2][ML][96] (B/C paired)
                 const float* __restrict__ A0, const float* __restrict__ A1,
                 const float* __restrict__ D0, const float* __restrict__ D1,
                 fp16* __restrict__ yout)         // [ML][2*DIN]
{
    __shared__ unsigned short sy[32][16];

    const int tid  = threadIdx.x;
    const int wid  = tid >> 5;
    const int lane = tid & 31;
    const int half = lane >> 4;
    const int s    = lane & 15;

    const int dg  = blockIdx.x & 127;
    const int b   = (blockIdx.x >> 7) & 1;
    const int dir = blockIdx.x >> 8;
    const int dloc = wid * 2 + half;
    const int d    = dg * 16 + dloc;

    const float* Alog = dir ? A1 : A0;
    const float Av = -__expf(Alog[d * DST + s]);
    const float Dd = (dir ? D1 : D0)[d];
    float h = 0.f;
    const bool w0lane = (s == 0);

    const size_t base = (size_t)b * LS;
    const int l0 = dir ? (LS - 1) : 0;
    const int step = dir ? -1 : 1;

    const float* pDtu = dtu + ((size_t)dir * ML * DIN + (base + l0) * DIN + d) * 2;
    const fp16*  pSz  = sz16 + (size_t)dir * ML * DIN + (base + l0) * DIN + d;
    const float* pBC  = xdbl + (size_t)dir * ML * 96 + (base + l0) * 96 + RDT + 2 * s;
    const ptrdiff_t sDtu = (ptrdiff_t)step * DIN * 2;
    const ptrdiff_t sSz  = (ptrdiff_t)step * DIN;
    const ptrdiff_t sBC  = (ptrdiff_t)step * 96;

    float2 du = *(const float2*)pDtu;
    float2 bc = *(const float2*)pBC;
    float zv  = __half2float(*pSz);

    for (int it = 0; it < LS; it++) {
        const bool more = (it + 1 < LS);
        float2 dun = more ? *(const float2*)(pDtu + sDtu) : du;
        float2 bcn = more ? *(const float2*)(pBC + sBC)   : bc;
        float zn   = more ? __half2float(*(pSz + sSz)) : zv;

        h = h * __expf(du.x * Av) + du.x * du.y * bc.x;
        float y = h * bc.y;
        y += __shfl_xor_sync(0xffffffffu, y, 8);
        y += __shfl_xor_sync(0xffffffffu, y, 4);
        y += __shfl_xor_sync(0xffffffffu, y, 2);
        y += __shfl_xor_sync(0xffffffffu, y, 1);
        if (w0lane) {
            float yv = (y + du.y * Dd) * zv;
            sy[it & 31][dloc] = __half_as_ushort(__float2half_rn(yv));
        }
        if ((it & 31) == 31) {
            __syncthreads();
            const int row = tid >> 3;
            const int cp  = tid & 7;
            const int itr = (it - 31) + row;
            const int gl  = l0 + step * itr;
            const size_t go = (base + (size_t)gl) * (2 * DIN) + dir * DIN + dg * 16 + 2 * cp;
            *(uint32_t*)(yout + go) = *(const uint32_t*)&sy[row][2 * cp];
            __syncthreads();
        }
        pDtu += sDtu; pSz += sSz; pBC += sBC;
        du = dun; bc = bcn; zv = zn;
    }
}

// ---------------- layernorm from xsum -> fp16 ln ----------------------------------
__global__ void ln_kernel(const float* __restrict__ xsum,
                          const float* __restrict__ g,
                          const float* __restrict__ bta,
                          fp16* __restrict__ lnout)
{
    int row = blockIdx.x;
    size_t off4 = (size_t)row * (DM / 4) + threadIdx.x;
    float4 v = ((const float4*)xsum)[off4];

    float s  = v.x + v.y + v.z + v.w;
    float sq = v.x*v.x + v.y*v.y + v.z*v.z + v.w*v.w;
    #pragma unroll
    for (int o = 16; o >= 1; o >>= 1) {
        s  += __shfl_xor_sync(0xffffffffu, s, o);
        sq += __shfl_xor_sync(0xffffffffu, sq, o);
    }
    __shared__ float ss[8], ssq[8];
    int warp = threadIdx.x >> 5, lane = threadIdx.x & 31;
    if (lane == 0) { ss[warp] = s; ssq[warp] = sq; }
    __syncthreads();
    __shared__ float sh_mean, sh_inv;
    if (threadIdx.x == 0) {
        float ts = 0.f, tq = 0.f;
        #pragma unroll
        for (int w = 0; w < 8; w++) { ts += ss[w]; tq += ssq[w]; }
        float mean = ts / DM;
        float var = tq / DM - mean * mean;
        sh_mean = mean;
        sh_inv = rsqrtf(var + 1e-5f);
    }
    __syncthreads();
    float mean = sh_mean, inv = sh_inv;
    float4 gv = ((const float4*)g)[threadIdx.x];
    float4 bv = ((const float4*)bta)[threadIdx.x];
    float o0 = (v.x - mean) * inv * gv.x + bv.x;
    float o1 = (v.y - mean) * inv * gv.y + bv.y;
    float o2 = (v.z - mean) * inv * gv.z + bv.z;
    float o3 = (v.w - mean) * inv * gv.w + bv.w;
    uint2 u;
    u.x = (uint32_t)__half_as_ushort(__float2half_rn(o0)) |
          ((uint32_t)__half_as_ushort(__float2half_rn(o1)) << 16);
    u.y = (uint32_t)__half_as_ushort(__float2half_rn(o2)) |
          ((uint32_t)__half_as_ushort(__float2half_rn(o3)) << 16);
    size_t off = (size_t)row * DM + threadIdx.x * 4;
    *(uint2*)(lnout + off) = u;
}

// ---------------- host orchestration ----------------------------------------------
extern "C" void kernel_launch(void* const* d_in, const int* in_sizes, int n_in,
                              void* d_out, int out_size)
{
    (void)in_sizes; (void)n_in; (void)out_size;

    const float* x = (const float*)d_in[0];
    const float* in_w[2]   = { (const float*)d_in[1],  (const float*)d_in[10] };
    const float* conv_w[2] = { (const float*)d_in[2],  (const float*)d_in[11] };
    const float* conv_b[2] = { (const float*)d_in[3],  (const float*)d_in[12] };
    const float* x_w[2]    = { (const float*)d_in[4],  (const float*)d_in[13] };
    const float* dt_w[2]   = { (const float*)d_in[5],  (const float*)d_in[14] };
    const float* dt_b[2]   = { (const float*)d_in[6],  (const float*)d_in[15] };
    const float* A_log[2]  = { (const float*)d_in[7],  (const float*)d_in[16] };
    const float* Dp[2]     = { (const float*)d_in[8],  (const float*)d_in[17] };
    const float* out_w[2]  = { (const float*)d_in[9],  (const float*)d_in[18] };
    const float* ff_ln_g = (const float*)d_in[19];
    const float* ff_ln_b = (const float*)d_in[20];
    const float* ff_w1   = (const float*)d_in[21];
    const float* ff_b1   = (const float*)d_in[22];
    const float* ff_w2   = (const float*)d_in[23];
    const float* ff_b2   = (const float*)d_in[24];

    float *xdbl, *dtu, *xsum;
    fp16 *xz16, *xc16, *sz16, *x16, *y16, *ln16, *f116;
    fp16 *inw16, *outw16c, *w116, *w216;
    cudaGetSymbolAddress((void**)&xz16, g_xz16);
    cudaGetSymbolAddress((void**)&xc16, g_xc16);
    cudaGetSymbolAddress((void**)&xdbl, g_xdbl);
    cudaGetSymbolAddress((void**)&dtu,  g_dtu);
    cudaGetSymbolAddress((void**)&sz16, g_sz16);
    cudaGetSymbolAddress((void**)&xsum, g_xsum);
    cudaGetSymbolAddress((void**)&x16,  g_x16);
    cudaGetSymbolAddress((void**)&y16,  g_y16);
    cudaGetSymbolAddress((void**)&ln16, g_ln16);
    cudaGetSymbolAddress((void**)&f116, g_f116);
    cudaGetSymbolAddress((void**)&inw16,   g_inw16);
    cudaGetSymbolAddress((void**)&outw16c, g_outw16c);
    cudaGetSymbolAddress((void**)&w116, g_w116);
    cudaGetSymbolAddress((void**)&w216, g_w216);

    cudaFuncSetAttribute(mma_gemm2, cudaFuncAttributeMaxDynamicSharedMemorySize, DSMEM2);

    const size_t szINW  = (size_t)2 * DIN * DM;

    dim3 blk(256);

    // idx 0-2: converts needed for in-proj
    wcvt_kernel<<<(ML*DM/4 + 255)/256, blk>>>(x, x16, ML*DM/4);
    wcvt_kernel<<<((int)szINW/4 + 255)/256, blk>>>(in_w[0], inw16,         (int)szINW/4);
    wcvt_kernel<<<((int)szINW/4 + 255)/256, blk>>>(in_w[1], inw16 + szINW, (int)szINW/4);

    // idx 3 (profiled): merged in-proj -> fp16 xz, M=4096, N=8192, K=1024
    mma_gemm2<<<dim3(64, 32, 1), blk, DSMEM2>>>(
        x16, DM, inw16, DM,
        nullptr, nullptr, nullptr, xz16,
        8192, DM, 0, 0, 0, 0);

    // remaining weight converts
    wcvt_kernel<<<(DFF*DM/4 + 255)/256, blk>>>(ff_w1, w116, DFF*DM/4);
    wcvt_out_kernel<<<(DM*DIN/4 + 255)/256, blk>>>(out_w[0], outw16c, 0);
    wcvt_out_kernel<<<(DM*DIN/4 + 255)/256, blk>>>(out_w[1], outw16c, 1);
    wcvt_kernel<<<(DM*DFF/4 + 255)/256, blk>>>(ff_w2, w216, DM*DFF/4);

    // conv (both dirs), fp16 in/out
    conv_kernel<<<(2*ML*DIN/4 + 255)/256, blk>>>(xz16, conv_w[0], conv_w[1],
                                                 conv_b[0], conv_b[1], xc16);

    // xdbl (both dirs), fp16 A, B/C interleaved
    xdbl_gemm<<<dim3(ML/32, 1, 2), dim3(128)>>>(xc16, x_w[0], x_w[1], xdbl);

    // dt (both dirs) -> (dt,u) pairs + silu(z) fp16
    dt_gemm<<<dim3(DIN/128, ML/128, 2), blk>>>(xdbl, xc16, xz16, dt_w[0], dt_w[1],
                                               dt_b[0], dt_b[1], dtu, sz16);

    // scan (both dirs) -> y16 [ML][dir*2048+d]
    scan_kernel<<<512, blk>>>(dtu, sz16, xdbl, A_log[0], A_log[1],
                              Dp[0], Dp[1], y16);

    // merged out-proj: xsum = x + y16 @ (0.5*outw_cat)^T, M=4096, N=1024, K=4096
    mma_gemm2<<<dim3(8, 32, 1), blk, DSMEM2>>>(
        y16, 2*DIN, outw16c, 2*DIN,
        nullptr, x, xsum, nullptr,
        DM, 2*DIN, 0, 0, 0, 0);

    // layernorm from xsum
    ln_kernel<<<ML, blk>>>(xsum, ff_ln_g, ff_ln_b, ln16);

    // ff1 = silu(ln @ ff_w1^T + b1) -> fp16
    mma_gemm2<<<dim3(32, 32, 1), blk, DSMEM2>>>(
        ln16, DM, w116, DM,
        ff_b1, nullptr, nullptr, f116,
        DFF, DM, 1, 0, 0, 0);

    // out = xsum + (ff1 @ ff_w2^T + b2)
    mma_gemm2<<<dim3(8, 32, 1), blk, DSMEM2>>>(
        f116, DFF, w216, DFF,
        ff_b2, xsum, (float*)d_out, nullptr,
        DM, DFF, 0, 0, 0, 0);
}